// round 16
// baseline (speedup 1.0000x reference)
#include <cuda_runtime.h>
#include <cuda_fp16.h>
#include <cstdint>

__device__ __forceinline__ unsigned h2bits(float a, float b) {
    __half2 h = __floats2half2_rn(a, b);
    return *reinterpret_cast<unsigned*>(&h);
}
__device__ __forceinline__ float2 h2unpack(unsigned u) {
    return __half22float2(*reinterpret_cast<__half2*>(&u));
}
__device__ __forceinline__ void mma16(float d[4], const unsigned a[4],
                                      unsigned b0, unsigned b1) {
    asm("mma.sync.aligned.m16n8k16.row.col.f32.f16.f16.f32 "
        "{%0,%1,%2,%3},{%4,%5,%6,%7},{%8,%9},{%0,%1,%2,%3};"
        : "+f"(d[0]), "+f"(d[1]), "+f"(d[2]), "+f"(d[3])
        : "r"(a[0]), "r"(a[1]), "r"(a[2]), "r"(a[3]), "r"(b0), "r"(b1));
}
__device__ __forceinline__ void ldsm_x4(unsigned a[4], unsigned addr) {
    asm volatile("ldmatrix.sync.aligned.m8n8.x4.shared.b16 {%0,%1,%2,%3}, [%4];"
                 : "=r"(a[0]), "=r"(a[1]), "=r"(a[2]), "=r"(a[3]) : "r"(addr));
}
__device__ __forceinline__ unsigned smem_u32(const void* p) {
    return (unsigned)__cvta_generic_to_shared(p);
}
__device__ __forceinline__ void cp4z(unsigned dst, const void* src, bool ok) {
    int sz = ok ? 4 : 0;
    asm volatile("cp.async.ca.shared.global [%0], [%1], 4, %2;" :: "r"(dst), "l"(src), "r"(sz));
}
__device__ __forceinline__ void cp16z(unsigned dst, const void* src, bool ok) {
    int sz = ok ? 16 : 0;
    asm volatile("cp.async.cg.shared.global [%0], [%1], 16, %2;" :: "r"(dst), "l"(src), "r"(sz));
}
__device__ __forceinline__ void cp16w(unsigned dst, const void* src) {
    asm volatile("cp.async.ca.shared.global [%0], [%1], 16;" :: "r"(dst), "l"(src));
}
__device__ __forceinline__ void cp_commit() { asm volatile("cp.async.commit_group;"); }
__device__ __forceinline__ void cp_wait1() { asm volatile("cp.async.wait_group 1;"); }
__device__ __forceinline__ void cp_wait0() { asm volatile("cp.async.wait_group 0;"); }

// ----- scratch -----
__device__ float g_w4 [8388608];
__device__ float g_iw1[2097152];
__device__ unsigned g_w1h  [1048576];
__device__ unsigned g_cat2h[8388608];
__device__ unsigned g_w2h  [4194304];
__device__ unsigned g_cat3h[8388608];
__device__ unsigned g_w3h  [4194304];
__device__ unsigned g_cat4h[8388608];
__device__ unsigned g_w4h  [4194304];
__device__ unsigned g_c4h  [4194304];
__device__ unsigned g_c5h  [4194304];
__device__ unsigned g_ic4h [4194304];
__device__ unsigned g_ic3h [4194304];
__device__ unsigned g_ic2h [4194304];
__device__ unsigned g_ic1h [4194304];
__device__ unsigned g_wp1 [  1152];
__device__ unsigned g_wpd2[  2304];
__device__ unsigned g_wpd1[  1152];
__device__ unsigned g_wp2 [  36864];
__device__ unsigned g_wp3 [ 331776];
__device__ unsigned g_wp4 [5308416];
__device__ unsigned g_wpd4[ 663552];
__device__ unsigned g_wpd3[  73728];

__global__ void pack_w_k(const float* __restrict__ w, unsigned* __restrict__ out,
                         int Cin, int Cout, int CoutPad, int K2) {
    __shared__ float sm[32][91];
    const int co0 = blockIdx.x * 32, kj0 = blockIdx.y * 32;
    const int ci2_lo = kj0 / 9, i_lo = ci2_lo * 18, Klen = Cin * 9;
    const int tid = threadIdx.x;
    for (int t = tid; t < 32 * 90; t += 256) {
        int r = t / 90, c = t - r * 90;
        int co = co0 + r, i = i_lo + c;
        sm[r][c] = (co < Cout && i < Klen) ? w[(long long)co * Klen + i] : 0.f;
    }
    __syncthreads();
    for (int t = tid; t < 1024; t += 256) {
        int kr = t >> 5, cl = t & 31, kj = kj0 + kr;
        if (kj >= K2 || co0 + cl >= CoutPad) continue;
        int ci2 = kj / 9, j = kj - ci2 * 9, ri = (ci2 - ci2_lo) * 18 + j;
        out[(long long)kj * CoutPad + co0 + cl] = h2bits(sm[cl][ri], sm[cl][ri + 9]);
    }
}
__global__ void pack_wL_k(const float* __restrict__ w, unsigned* __restrict__ out,
                          int Cin, int Cout) {
    __shared__ float sm[32][145];
    const int co0 = blockIdx.x * 32, kt = blockIdx.y, tid = threadIdx.x;
    for (int t = tid; t < 32 * 144; t += 256) {
        int r = t / 144, c = t - r * 144;
        sm[r][c] = w[((long long)(co0 + r) * Cin + kt * 16) * 9 + c];
    }
    __syncthreads();
    for (int t = tid; t < 2304; t += 256) {
        int wd = t & 7, c = (t >> 3) & 31, tap = t >> 8;
        out[(((long long)kt * 9 + tap) * Cout + co0 + c) * 8 + wd] =
            h2bits(sm[c][(2 * wd) * 9 + tap], sm[c][(2 * wd + 1) * 9 + tap]);
    }
}

__global__ void wt_k(const float* __restrict__ in, int Ho, int Wo,
                     unsigned* __restrict__ outH2, int total) {
    int idx = blockIdx.x * blockDim.x + threadIdx.x;
    if (idx >= total) return;
    int wo = idx % Wo; int t = idx / Wo;
    int ho = t % Ho;  int b = t / Ho;
    int Wi = 2 * Wo;
    const float* p = in + ((long long)b * (2 * Ho) + 2 * ho) * Wi + 2 * wo;
    float x00 = p[0], x01 = p[1], x10 = p[Wi], x11 = p[Wi + 1];
    float y0 = 0.25f * (x00 + x01 + x10 + x11);
    float y1 = 0.25f * (x00 + x01 - x10 - x11) + 0.5f;
    float y2 = 0.25f * (x00 - x01 + x10 - x11) + 0.5f;
    float y3 = 0.25f * (x00 - x01 - x10 + x11) + 0.5f;
    long long s = (long long)Ho * Wo;
    long long hb = ((long long)b * 2 * Ho + ho) * Wo + wo;
    outH2[hb] = h2bits(y0, y1);
    outH2[hb + s] = h2bits(y2, y3);
}

__global__ void iwt_h2_k(const unsigned* __restrict__ inH2, int pairs, int H, int W,
                         unsigned* __restrict__ outH2, int gTot, int gOff, int total) {
    int idx = blockIdx.x * blockDim.x + threadIdx.x;
    if (idx >= total) return;
    int w = idx % W; int t = idx / W;
    int h = t % H;  t /= H;
    int g = t % pairs; int b = t / pairs;
    long long s = (long long)H * W;
    long long base = (((long long)b * (4 * pairs) + 4 * g) * H + h) * W + w;
    float x00[2], x01[2], x10[2], x11[2];
#pragma unroll
    for (int cc = 0; cc < 2; cc++) {
        float2 fa = h2unpack(inH2[base + (2 * cc) * s]);
        float2 fb = h2unpack(inH2[base + (2 * cc + 1) * s]);
        float y0 = fa.x, t1 = 2.f * fa.y - 1.f, t2 = 2.f * fb.x - 1.f, t3 = 2.f * fb.y - 1.f;
        x00[cc] = y0 + 0.5f * ( t1 + t2 + t3);
        x01[cc] = y0 + 0.5f * ( t1 - t2 - t3);
        x10[cc] = y0 + 0.5f * (-t1 + t2 - t3);
        x11[cc] = y0 + 0.5f * (-t1 - t2 + t3);
    }
    int W2 = 2 * W;
    long long ob = (((long long)b * gTot + gOff + g) * (2 * H) + 2 * h) * W2 + 2 * w;
    uint2 r0, r1;
    r0.x = h2bits(x00[0], x00[1]); r0.y = h2bits(x01[0], x01[1]);
    r1.x = h2bits(x10[0], x10[1]); r1.y = h2bits(x11[0], x11[1]);
    *reinterpret_cast<uint2*>(outH2 + ob) = r0;
    *reinterpret_cast<uint2*>(outH2 + ob + W2) = r1;
}

__global__ void iwt_sig_k(const float* __restrict__ in, int H, int W,
                          float* __restrict__ out, int total) {
    int idx = blockIdx.x * blockDim.x + threadIdx.x;
    if (idx >= total) return;
    int w = idx % W; int t = idx / W;
    int h = t % H;  int b = t / H;
    long long s = (long long)H * W;
    long long ib = (((long long)b * 4) * H + h) * W + w;
    float y0 = in[ib];
    float t1 = 2.f * in[ib + s] - 1.f, t2 = 2.f * in[ib + 2 * s] - 1.f, t3 = 2.f * in[ib + 3 * s] - 1.f;
    float x00 = y0 + 0.5f * ( t1 + t2 + t3);
    float x01 = y0 + 0.5f * ( t1 - t2 - t3);
    float x10 = y0 + 0.5f * (-t1 + t2 - t3);
    float x11 = y0 + 0.5f * (-t1 - t2 + t3);
    x00 = 1.f / (1.f + expf(-x00)); x01 = 1.f / (1.f + expf(-x01));
    x10 = 1.f / (1.f + expf(-x10)); x11 = 1.f / (1.f + expf(-x11));
    int W2 = 2 * W;
    float* o = out + ((long long)b * (2 * H) + 2 * h) * W2 + 2 * w;
    o[0] = x00; o[1] = x01; o[W2] = x10; o[W2 + 1] = x11;
}

// ---------------------------------------------------------------------------
// Pipelined fp16 mma conv: COTILE=64, 256 thr, 2 blocks/SM, double-buffered.
// Patch stored pair-interleaved: word[2*(g4*G2 + y*PW2 + x) + h] = value of
// channel-group g4+4h at (y, x).  B fragment = one LDS.64 (b0=g, b1=g+4).
// G2=372 (== 4 mod 16) makes LDS.64 bank-pair = (8*tig + 2*gid) mod 32 -> perm.
// A via ldmatrix.x4 from wsm[9][64][12-word rows].
// ---------------------------------------------------------------------------
__global__ __launch_bounds__(256, 2)
void conv_mma_pipe_k(const unsigned* __restrict__ inH2, int gInTot, int kTiles,
                     const unsigned* __restrict__ wp, int coutTot,
                     const float* __restrict__ bias,
                     unsigned* __restrict__ outH2, int gOutTot, int gOutOff,
                     unsigned* __restrict__ wtH2, float* __restrict__ wt32,
                     const float* __restrict__ addend, int addCtot,
                     int H, int W) {
    constexpr int PW2 = 20, G2 = 372;            // 18*20=360, pad 12 -> 372 == 4 (mod 16)
    constexpr int PATCH_W = 4 * G2 * 2;          // 2976 words
    constexpr int WSM_W = 9 * 64 * 12;           // 6912
    constexpr int STAGE = PATCH_W + WSM_W;       // 9888
    extern __shared__ unsigned sm[];
    const int tid = threadIdx.x, lane = tid & 31, warp = tid >> 5;
    const int gid = lane >> 2, tig = lane & 3;
    const int mwarp = warp & 1, nwarp = warp >> 1;
    const int tilesX = W >> 4;
    const int tx0 = (blockIdx.x % tilesX) << 4, ty0 = (blockIdx.x / tilesX) << 4;
    const int co0 = blockIdx.y << 6, b = blockIdx.z;
    const int HW = H * W;
    const long long inBase = (long long)b * gInTot * HW;

    float acc[2][8][4];
#pragma unroll
    for (int mt = 0; mt < 2; mt++)
#pragma unroll
        for (int nt = 0; nt < 8; nt++)
#pragma unroll
            for (int r = 0; r < 4; r++) acc[mt][nt][r] = 0.f;

    auto stage = [&](int kt, int buf) {
        unsigned pb = smem_u32(sm + buf * STAGE);
        unsigned wb = pb + PATCH_W * 4;
        const int g0 = kt * 8;
        // patch: 8 g x 18 y x 20 x, 4B cp.async, pair-interleaved dst
        for (int idx = tid; idx < 2880; idx += 256) {
            int x = idx % 20;
            int t = idx / 20;
            int y = t % 18;
            int g = t / 18;
            int g4 = g & 3, h = g >> 2;
            int gy = ty0 - 1 + y, gx = tx0 - 2 + x;
            bool ok = (unsigned)gy < (unsigned)H && (unsigned)gx < (unsigned)W;
            const unsigned* src = inH2 + inBase + (long long)(g0 + g) * HW + (ok ? (gy * W + gx) : 0);
            unsigned widx = (unsigned)((g4 * G2 + y * PW2 + x) * 2 + h);
            cp4z(pb + widx * 4u, src, ok);
        }
        for (int idx = tid; idx < 1152; idx += 256) {
            int half = idx & 1, row = idx >> 1;     // row = j*64 + co
            int j = row >> 6, co = row & 63;
            const unsigned* src = wp + (((long long)kt * 9 + j) * coutTot + co0 + co) * 8 + half * 4;
            cp16w(wb + (unsigned)((j * 64 + co) * 12 + half * 4) * 4u, src);
        }
    };
    auto compute = [&](int buf) {
        const unsigned* pbuf = sm + buf * STAGE;
        unsigned wbase = smem_u32(sm + buf * STAGE + PATCH_W);
        int lr = lane & 7, hb = (lane >> 3) & 1, kq = (lane >> 4) & 1;
        unsigned aoff0 = wbase + (unsigned)(((mwarp * 32 + hb * 8 + lr) * 12 + kq * 4) << 2);
        unsigned aoff1 = aoff0 + (16 * 12) * 4;
#pragma unroll
        for (int j = 0; j < 9; j++) {
            const int dy = j / 3, dx = j - 3 * dy;
            unsigned a0[4], a1[4];
            ldsm_x4(a0, aoff0 + (unsigned)(j * 768 * 4));
            ldsm_x4(a1, aoff1 + (unsigned)(j * 768 * 4));
            // base pidx for this thread/tap: x index = gid + dx + 1
            const unsigned* pbB = pbuf + 2 * (tig * G2 + dy * PW2 + dx + gid + 1);
#pragma unroll
            for (int nt = 0; nt < 8; nt++) {
                int pix = nwarp * 64 + nt * 8;
                int off = 2 * ((pix >> 4) * PW2 + (pix & 15));
                uint2 bb = *reinterpret_cast<const uint2*>(pbB + off);
                mma16(acc[0][nt], a0, bb.x, bb.y);
                mma16(acc[1][nt], a1, bb.x, bb.y);
            }
        }
    };

    stage(0, 0); cp_commit();
    for (int kt = 0; kt < kTiles; kt++) {
        int cur = kt & 1;
        if (kt + 1 < kTiles) { stage(kt + 1, cur ^ 1); cp_commit(); cp_wait1(); }
        else cp_wait0();
        __syncthreads();
        compute(cur);
        __syncthreads();
    }

    const int Ho = H >> 1, Wo = W >> 1;
#pragma unroll
    for (int mt = 0; mt < 2; mt++)
#pragma unroll
        for (int rr = 0; rr < 2; rr++) {
            int co = co0 + mwarp * 32 + mt * 16 + rr * 8 + gid;
            float bv = bias[co];
#pragma unroll
            for (int np = 0; np < 4; np++) {
                int ntT = (np & 1) | ((np >> 1) << 2);
                int ntB = ntT + 2;
                int pixT = nwarp * 64 + ntT * 8;
                int oy = ty0 + (pixT >> 4);
                int ox = tx0 + (pixT & 15) + 2 * tig;
                float x00 = acc[mt][ntT][rr * 2] + bv, x01 = acc[mt][ntT][rr * 2 + 1] + bv;
                float x10 = acc[mt][ntB][rr * 2] + bv, x11 = acc[mt][ntB][rr * 2 + 1] + bv;
                if (addend) {
                    const float* ap = addend + (((long long)b * addCtot + co) * H + oy) * W + ox;
                    x00 += ap[0]; x01 += ap[1]; x10 += ap[W]; x11 += ap[W + 1];
                }
                x00 = x00 > 0.f ? x00 : 0.2f * x00;
                x01 = x01 > 0.f ? x01 : 0.2f * x01;
                x10 = x10 > 0.f ? x10 : 0.2f * x10;
                x11 = x11 > 0.f ? x11 : 0.2f * x11;
                float sT0 = __shfl_xor_sync(0xffffffffu, x00, 4);
                float sT1 = __shfl_xor_sync(0xffffffffu, x01, 4);
                float sB0 = __shfl_xor_sync(0xffffffffu, x10, 4);
                float sB1 = __shfl_xor_sync(0xffffffffu, x11, 4);
                if ((gid & 1) == 0) {
                    long long ob = (((long long)b * gOutTot + gOutOff + (co >> 1)) * H + oy) * W + ox;
                    uint2 wT, wB;
                    wT.x = h2bits(x00, sT0); wT.y = h2bits(x01, sT1);
                    wB.x = h2bits(x10, sB0); wB.y = h2bits(x11, sB1);
                    *reinterpret_cast<uint2*>(outH2 + ob)     = wT;
                    *reinterpret_cast<uint2*>(outH2 + ob + W) = wB;
                }
                if (wtH2) {
                    float y0 = 0.25f * (x00 + x01 + x10 + x11);
                    float y1 = 0.25f * (x00 + x01 - x10 - x11) + 0.5f;
                    float y2 = 0.25f * (x00 - x01 + x10 - x11) + 0.5f;
                    float y3 = 0.25f * (x00 - x01 - x10 + x11) + 0.5f;
                    int ho = oy >> 1, wo = ox >> 1;
                    long long wbs = (((long long)b * (2 * coutTot) + 2 * co) * Ho + ho) * Wo + wo;
                    wtH2[wbs] = h2bits(y0, y1);
                    wtH2[wbs + (long long)Ho * Wo] = h2bits(y2, y3);
                    if (wt32) {
                        long long fb = (((long long)b * (4 * coutTot) + 4 * co) * Ho + ho) * Wo + wo;
                        long long sw = (long long)Ho * Wo;
                        wt32[fb] = y0; wt32[fb + sw] = y1;
                        wt32[fb + 2 * sw] = y2; wt32[fb + 3 * sw] = y3;
                    }
                }
            }
        }
}

// ----- small-layer mma conv (COTILE=16), optional fused wt -----
__global__ __launch_bounds__(128, 4)
void conv_mma16_k(const unsigned* __restrict__ inH2, int gInTot, int gInAct, int kTiles,
                  const unsigned* __restrict__ wp, int coutPad,
                  const float* __restrict__ bias,
                  float* __restrict__ out32, int out32Ctot,
                  unsigned* __restrict__ outH2, int gOutTot, int gOutOff,
                  unsigned* __restrict__ wtH2, int coutTot,
                  int H, int W, int coutAct) {
    __shared__ unsigned patch[8][18][20];
    __shared__ unsigned wsm[9][8][24];
    const int tid = threadIdx.x, lane = tid & 31, warp = tid >> 5;
    const int gid = lane >> 2, tig = lane & 3;
    const int tilesX = W >> 4;
    const int tx0 = (blockIdx.x % tilesX) << 4, ty0 = (blockIdx.x / tilesX) << 4;
    const int co0 = blockIdx.y * 16, b = blockIdx.z;
    const int HW = H * W;
    float acc[8][4];
#pragma unroll
    for (int nt = 0; nt < 8; nt++)
#pragma unroll
        for (int r = 0; r < 4; r++) acc[nt][r] = 0.f;
    const long long inBase = (long long)b * gInTot * HW;
    for (int kt = 0; kt < kTiles; kt++) {
        const int g0 = kt * 8;
        __syncthreads();
        for (int idx = tid; idx < 8 * 324; idx += 128) {
            int g = idx / 324, rem = idx - g * 324;
            int r = rem / 18, c = rem - r * 18;
            int gy = ty0 - 1 + r, gx = tx0 - 1 + c;
            unsigned v = 0;
            int aG = g0 + g;
            if (aG < gInAct && (unsigned)gy < (unsigned)H && (unsigned)gx < (unsigned)W)
                v = inH2[inBase + (long long)aG * HW + gy * W + gx];
            patch[g][r][c] = v;
        }
        for (int idx = tid; idx < 576; idx += 128) {
            int co2 = idx % 8, t = idx / 8;
            int kg = t % 8, j = t / 8;
            uint2 v = *reinterpret_cast<const uint2*>(
                wp + ((long long)(g0 + kg) * 9 + j) * coutPad + co0 + 2 * co2);
            *reinterpret_cast<uint2*>(&wsm[j][kg][2 * co2]) = v;
        }
        __syncthreads();
#pragma unroll
        for (int j = 0; j < 9; j++) {
            const int dy = j / 3, dx = j - 3 * dy;
            unsigned a[4];
            a[0] = wsm[j][tig][gid];     a[1] = wsm[j][tig][gid + 8];
            a[2] = wsm[j][tig + 4][gid]; a[3] = wsm[j][tig + 4][gid + 8];
            const unsigned* pb0 = &patch[tig][dy][dx + gid];
            const unsigned* pb1 = &patch[tig + 4][dy][dx + gid];
#pragma unroll
            for (int nt = 0; nt < 8; nt++) {
                int pix = warp * 64 + nt * 8;
                int off = (pix >> 4) * 20 + (pix & 15);
                mma16(acc[nt], a, pb0[off], pb1[off]);
            }
        }
    }
    const int Ho = H >> 1, Wo = W >> 1;
#pragma unroll
    for (int rr = 0; rr < 2; rr++) {
        int co = co0 + rr * 8 + gid;
        float bv = (co < coutAct) ? bias[co] : 0.f;
#pragma unroll
        for (int np = 0; np < 4; np++) {
            int ntT = (np & 1) | ((np >> 1) << 2);
            int ntB = ntT + 2;
            int pixT = warp * 64 + ntT * 8;
            int oy = ty0 + (pixT >> 4);
            int ox = tx0 + (pixT & 15) + 2 * tig;
            float x00 = acc[ntT][rr * 2] + bv, x01 = acc[ntT][rr * 2 + 1] + bv;
            float x10 = acc[ntB][rr * 2] + bv, x11 = acc[ntB][rr * 2 + 1] + bv;
            x00 = x00 > 0.f ? x00 : 0.2f * x00;
            x01 = x01 > 0.f ? x01 : 0.2f * x01;
            x10 = x10 > 0.f ? x10 : 0.2f * x10;
            x11 = x11 > 0.f ? x11 : 0.2f * x11;
            if (out32 && co < coutAct) {
                float* op = out32 + (((long long)b * out32Ctot + co) * H + oy) * W + ox;
                *reinterpret_cast<float2*>(op)     = make_float2(x00, x01);
                *reinterpret_cast<float2*>(op + W) = make_float2(x10, x11);
            }
            float sT0 = __shfl_xor_sync(0xffffffffu, x00, 4);
            float sT1 = __shfl_xor_sync(0xffffffffu, x01, 4);
            float sB0 = __shfl_xor_sync(0xffffffffu, x10, 4);
            float sB1 = __shfl_xor_sync(0xffffffffu, x11, 4);
            if (outH2 && (gid & 1) == 0) {
                long long ob = (((long long)b * gOutTot + gOutOff + (co >> 1)) * H + oy) * W + ox;
                uint2 wT, wB;
                wT.x = h2bits(x00, sT0); wT.y = h2bits(x01, sT1);
                wB.x = h2bits(x10, sB0); wB.y = h2bits(x11, sB1);
                *reinterpret_cast<uint2*>(outH2 + ob)     = wT;
                *reinterpret_cast<uint2*>(outH2 + ob + W) = wB;
            }
            if (wtH2 && co < coutAct) {
                float y0 = 0.25f * (x00 + x01 + x10 + x11);
                float y1 = 0.25f * (x00 + x01 - x10 - x11) + 0.5f;
                float y2 = 0.25f * (x00 - x01 + x10 - x11) + 0.5f;
                float y3 = 0.25f * (x00 - x01 - x10 + x11) + 0.5f;
                int ho = oy >> 1, wo = ox >> 1;
                long long wbs = (((long long)b * (2 * coutTot) + 2 * co) * Ho + ho) * Wo + wo;
                wtH2[wbs] = h2bits(y0, y1);
                wtH2[wbs + (long long)Ho * Wo] = h2bits(y2, y3);
            }
        }
    }
}

extern "C" void kernel_launch(void* const* d_in, const int* in_sizes, int n_in,
                              void* d_out, int out_size) {
    const float* x        = (const float*)d_in[0];
    const float* conv1_w  = (const float*)d_in[1];
    const float* conv1_b  = (const float*)d_in[2];
    const float* conv2_w  = (const float*)d_in[3];
    const float* conv2_b  = (const float*)d_in[4];
    const float* conv3_w  = (const float*)d_in[5];
    const float* conv3_b  = (const float*)d_in[6];
    const float* conv4_w  = (const float*)d_in[7];
    const float* conv4_b  = (const float*)d_in[8];
    const float* convd1_w = (const float*)d_in[9];
    const float* convd1_b = (const float*)d_in[10];
    const float* convd2_w = (const float*)d_in[11];
    const float* convd2_b = (const float*)d_in[12];
    const float* convd3_w = (const float*)d_in[13];
    const float* convd3_b = (const float*)d_in[14];
    const float* convd4_w = (const float*)d_in[15];
    const float* convd4_b = (const float*)d_in[16];
    float* out = (float*)d_out;

    float *w4, *iw1;
    unsigned *w1h, *cat2h, *w2h, *cat3h, *w3h, *cat4h, *w4h, *c4h, *c5h;
    unsigned *ic4h, *ic3h, *ic2h, *ic1h;
    unsigned *wp1, *wp2, *wp3, *wp4, *wpd4, *wpd3, *wpd2, *wpd1;
    cudaGetSymbolAddress((void**)&w4, g_w4);
    cudaGetSymbolAddress((void**)&iw1, g_iw1);
    cudaGetSymbolAddress((void**)&w1h, g_w1h);
    cudaGetSymbolAddress((void**)&cat2h, g_cat2h);
    cudaGetSymbolAddress((void**)&w2h, g_w2h);
    cudaGetSymbolAddress((void**)&cat3h, g_cat3h);
    cudaGetSymbolAddress((void**)&w3h, g_w3h);
    cudaGetSymbolAddress((void**)&cat4h, g_cat4h);
    cudaGetSymbolAddress((void**)&w4h, g_w4h);
    cudaGetSymbolAddress((void**)&c4h, g_c4h);
    cudaGetSymbolAddress((void**)&c5h, g_c5h);
    cudaGetSymbolAddress((void**)&ic4h, g_ic4h);
    cudaGetSymbolAddress((void**)&ic3h, g_ic3h);
    cudaGetSymbolAddress((void**)&ic2h, g_ic2h);
    cudaGetSymbolAddress((void**)&ic1h, g_ic1h);
    cudaGetSymbolAddress((void**)&wp1, g_wp1);
    cudaGetSymbolAddress((void**)&wp2, g_wp2);
    cudaGetSymbolAddress((void**)&wp3, g_wp3);
    cudaGetSymbolAddress((void**)&wp4, g_wp4);
    cudaGetSymbolAddress((void**)&wpd4, g_wpd4);
    cudaGetSymbolAddress((void**)&wpd3, g_wpd3);
    cudaGetSymbolAddress((void**)&wpd2, g_wpd2);
    cudaGetSymbolAddress((void**)&wpd1, g_wpd1);

    const int SMEMP = 2 * (2976 + 6912) * 4;   // 79104 B
    static bool attrSet = false;
    if (!attrSet) {
        cudaFuncSetAttribute(conv_mma_pipe_k, cudaFuncAttributeMaxDynamicSharedMemorySize, SMEMP);
        attrSet = true;
    }
    const int B = 8;
    int tot;

    auto packS = [](const float* w, unsigned* outp, int Cin, int CinPad, int Cout, int CoutPad) {
        int K2 = (CinPad / 2) * 9;
        dim3 grid((CoutPad + 31) / 32, (K2 + 31) / 32);
        pack_w_k<<<grid, 256>>>(w, outp, Cin, Cout, CoutPad, K2);
    };
    auto packL = [](const float* w, unsigned* outp, int Cin, int Cout) {
        pack_wL_k<<<dim3(Cout / 32, Cin / 16), 256>>>(w, outp, Cin, Cout);
    };

    packS(conv1_w, wp1, 4, 16, 16, 16);
    packL(conv2_w, wp2, 64, 64);
    tot = B * 256 * 256;
    wt_k<<<(tot + 255) / 256, 256>>>(x, 256, 256, w1h, tot);
    conv_mma16_k<<<dim3(256, 1, 8), 128>>>(w1h, 2, 2, 1, wp1, 16, conv1_b,
                                           nullptr, 0, cat2h, 16, 0, w2h, 16, 256, 256, 16);
    packL(conv3_w, wp3, 256, 256);
    conv_mma_pipe_k<<<dim3(64, 1, 8), 256, SMEMP>>>(w2h, 32, 4, wp2, 64, conv2_b,
        cat3h, 64, 0, w3h, nullptr, nullptr, 0, 128, 128);      // <- ncu sample slot
    packL(conv4_w, wp4, 1024, 1024);
    packL(convd4_w, wpd4, 512, 256);
    packL(convd3_w, wpd3, 128, 64);
    packS(convd2_w, wpd2, 32, 32, 16, 16);
    packS(convd1_w, wpd1, 16, 16, 4, 16);

    conv_mma_pipe_k<<<dim3(16, 4, 8), 256, SMEMP>>>(w3h, 128, 16, wp3, 256, conv3_b,
        cat4h, 256, 0, w4h, w4, nullptr, 0, 64, 64);
    conv_mma_pipe_k<<<dim3(4, 16, 8), 256, SMEMP>>>(w4h, 512, 64, wp4, 1024, conv4_b,
        c4h, 512, 0, nullptr, nullptr, nullptr, 0, 32, 32);
    conv_mma_pipe_k<<<dim3(4, 16, 8), 256, SMEMP>>>(c4h, 512, 64, wp4, 1024, conv4_b,
        c5h, 512, 0, nullptr, nullptr, nullptr, 0, 32, 32);
    conv_mma_pipe_k<<<dim3(4, 16, 8), 256, SMEMP>>>(c5h, 512, 64, wp4, 1024, conv4_b,
        ic4h, 512, 0, nullptr, nullptr, w4, 1024, 32, 32);

    tot = B * 128 * 32 * 32;
    iwt_h2_k<<<(tot + 255) / 256, 256>>>(ic4h, 128, 32, 32, cat4h, 256, 128, tot);

    conv_mma_pipe_k<<<dim3(16, 4, 8), 256, SMEMP>>>(cat4h, 256, 32, wpd4, 256, convd4_b,
        ic3h, 128, 0, nullptr, nullptr, nullptr, 0, 64, 64);
    tot = B * 32 * 64 * 64;
    iwt_h2_k<<<(tot + 255) / 256, 256>>>(ic3h, 32, 64, 64, cat3h, 64, 32, tot);

    conv_mma_pipe_k<<<dim3(64, 1, 8), 256, SMEMP>>>(cat3h, 64, 8, wpd3, 64, convd3_b,
        ic2h, 32, 0, nullptr, nullptr, nullptr, 0, 128, 128);
    tot = B * 8 * 128 * 128;
    iwt_h2_k<<<(tot + 255) / 256, 256>>>(ic2h, 8, 128, 128, cat2h, 16, 8, tot);

    conv_mma16_k<<<dim3(256, 1, 8), 128>>>(cat2h, 16, 16, 2, wpd2, 16, convd2_b,
                                           nullptr, 0, ic1h, 8, 0, nullptr, 16, 256, 256, 16);
    conv_mma16_k<<<dim3(256, 1, 8), 128>>>(ic1h, 8, 8, 1, wpd1, 16, convd1_b,
                                           iw1, 4, nullptr, 0, 0, nullptr, 4, 256, 256, 4);

    tot = B * 256 * 256;
    iwt_sig_k<<<(tot + 255) / 256, 256>>>(iw1, 256, 256, out, tot);

    (void)in_sizes; (void)n_in; (void)out_size;
}

// round 17
// speedup vs baseline: 1.3418x; 1.3418x over previous
#include <cuda_runtime.h>
#include <cuda_fp16.h>
#include <cstdint>

__device__ __forceinline__ unsigned h2bits(float a, float b) {
    __half2 h = __floats2half2_rn(a, b);
    return *reinterpret_cast<unsigned*>(&h);
}
__device__ __forceinline__ float2 h2unpack(unsigned u) {
    return __half22float2(*reinterpret_cast<__half2*>(&u));
}
__device__ __forceinline__ void mma16(float d[4], const unsigned a[4],
                                      unsigned b0, unsigned b1) {
    asm("mma.sync.aligned.m16n8k16.row.col.f32.f16.f16.f32 "
        "{%0,%1,%2,%3},{%4,%5,%6,%7},{%8,%9},{%0,%1,%2,%3};"
        : "+f"(d[0]), "+f"(d[1]), "+f"(d[2]), "+f"(d[3])
        : "r"(a[0]), "r"(a[1]), "r"(a[2]), "r"(a[3]), "r"(b0), "r"(b1));
}
__device__ __forceinline__ void ldsm_x4(unsigned a[4], unsigned addr) {
    asm volatile("ldmatrix.sync.aligned.m8n8.x4.shared.b16 {%0,%1,%2,%3}, [%4];"
                 : "=r"(a[0]), "=r"(a[1]), "=r"(a[2]), "=r"(a[3]) : "r"(addr));
}
__device__ __forceinline__ unsigned smem_u32(const void* p) {
    return (unsigned)__cvta_generic_to_shared(p);
}
__device__ __forceinline__ void cp16z(unsigned dst, const void* src, bool ok) {
    int sz = ok ? 16 : 0;
    asm volatile("cp.async.cg.shared.global [%0], [%1], 16, %2;" :: "r"(dst), "l"(src), "r"(sz));
}
__device__ __forceinline__ void cp16w(unsigned dst, const void* src) {   // L1-retaining (weights reused across blocks)
    asm volatile("cp.async.ca.shared.global [%0], [%1], 16;" :: "r"(dst), "l"(src));
}
__device__ __forceinline__ void cp_commit() { asm volatile("cp.async.commit_group;"); }
__device__ __forceinline__ void cp_wait1() { asm volatile("cp.async.wait_group 1;"); }
__device__ __forceinline__ void cp_wait0() { asm volatile("cp.async.wait_group 0;"); }

// ----- scratch -----
__device__ float g_w4 [8388608];
__device__ float g_iw1[2097152];
__device__ unsigned g_w1h  [1048576];
__device__ unsigned g_cat2h[8388608];
__device__ unsigned g_w2h  [4194304];
__device__ unsigned g_cat3h[8388608];
__device__ unsigned g_w3h  [4194304];
__device__ unsigned g_cat4h[8388608];
__device__ unsigned g_w4h  [4194304];
__device__ unsigned g_c4h  [4194304];
__device__ unsigned g_c5h  [4194304];
__device__ unsigned g_ic4h [4194304];
__device__ unsigned g_ic3h [4194304];
__device__ unsigned g_ic2h [4194304];
__device__ unsigned g_ic1h [4194304];
__device__ unsigned g_wp1 [  1152];
__device__ unsigned g_wpd2[  2304];
__device__ unsigned g_wpd1[  1152];
__device__ unsigned g_wp2 [  36864];
__device__ unsigned g_wp3 [ 331776];
__device__ unsigned g_wp4 [5308416];
__device__ unsigned g_wpd4[ 663552];
__device__ unsigned g_wpd3[  73728];

__global__ void pack_w_k(const float* __restrict__ w, unsigned* __restrict__ out,
                         int Cin, int Cout, int CoutPad, int K2) {
    __shared__ float sm[32][91];
    const int co0 = blockIdx.x * 32, kj0 = blockIdx.y * 32;
    const int ci2_lo = kj0 / 9, i_lo = ci2_lo * 18, Klen = Cin * 9;
    const int tid = threadIdx.x;
    for (int t = tid; t < 32 * 90; t += 256) {
        int r = t / 90, c = t - r * 90;
        int co = co0 + r, i = i_lo + c;
        sm[r][c] = (co < Cout && i < Klen) ? w[(long long)co * Klen + i] : 0.f;
    }
    __syncthreads();
    for (int t = tid; t < 1024; t += 256) {
        int kr = t >> 5, cl = t & 31, kj = kj0 + kr;
        if (kj >= K2 || co0 + cl >= CoutPad) continue;
        int ci2 = kj / 9, j = kj - ci2 * 9, ri = (ci2 - ci2_lo) * 18 + j;
        out[(long long)kj * CoutPad + co0 + cl] = h2bits(sm[cl][ri], sm[cl][ri + 9]);
    }
}
__global__ void pack_wL_k(const float* __restrict__ w, unsigned* __restrict__ out,
                          int Cin, int Cout) {
    __shared__ float sm[32][145];
    const int co0 = blockIdx.x * 32, kt = blockIdx.y, tid = threadIdx.x;
    for (int t = tid; t < 32 * 144; t += 256) {
        int r = t / 144, c = t - r * 144;
        sm[r][c] = w[((long long)(co0 + r) * Cin + kt * 16) * 9 + c];
    }
    __syncthreads();
    for (int t = tid; t < 2304; t += 256) {
        int wd = t & 7, c = (t >> 3) & 31, tap = t >> 8;
        out[(((long long)kt * 9 + tap) * Cout + co0 + c) * 8 + wd] =
            h2bits(sm[c][(2 * wd) * 9 + tap], sm[c][(2 * wd + 1) * 9 + tap]);
    }
}

__global__ void wt_k(const float* __restrict__ in, int Ho, int Wo,
                     unsigned* __restrict__ outH2, int total) {
    int idx = blockIdx.x * blockDim.x + threadIdx.x;
    if (idx >= total) return;
    int wo = idx % Wo; int t = idx / Wo;
    int ho = t % Ho;  int b = t / Ho;
    int Wi = 2 * Wo;
    const float* p = in + ((long long)b * (2 * Ho) + 2 * ho) * Wi + 2 * wo;
    float x00 = p[0], x01 = p[1], x10 = p[Wi], x11 = p[Wi + 1];
    float y0 = 0.25f * (x00 + x01 + x10 + x11);
    float y1 = 0.25f * (x00 + x01 - x10 - x11) + 0.5f;
    float y2 = 0.25f * (x00 - x01 + x10 - x11) + 0.5f;
    float y3 = 0.25f * (x00 - x01 - x10 + x11) + 0.5f;
    long long s = (long long)Ho * Wo;
    long long hb = ((long long)b * 2 * Ho + ho) * Wo + wo;
    outH2[hb] = h2bits(y0, y1);
    outH2[hb + s] = h2bits(y2, y3);
}

__global__ void iwt_h2_k(const unsigned* __restrict__ inH2, int pairs, int H, int W,
                         unsigned* __restrict__ outH2, int gTot, int gOff, int total) {
    int idx = blockIdx.x * blockDim.x + threadIdx.x;
    if (idx >= total) return;
    int w = idx % W; int t = idx / W;
    int h = t % H;  t /= H;
    int g = t % pairs; int b = t / pairs;
    long long s = (long long)H * W;
    long long base = (((long long)b * (4 * pairs) + 4 * g) * H + h) * W + w;
    float x00[2], x01[2], x10[2], x11[2];
#pragma unroll
    for (int cc = 0; cc < 2; cc++) {
        float2 fa = h2unpack(inH2[base + (2 * cc) * s]);
        float2 fb = h2unpack(inH2[base + (2 * cc + 1) * s]);
        float y0 = fa.x, t1 = 2.f * fa.y - 1.f, t2 = 2.f * fb.x - 1.f, t3 = 2.f * fb.y - 1.f;
        x00[cc] = y0 + 0.5f * ( t1 + t2 + t3);
        x01[cc] = y0 + 0.5f * ( t1 - t2 - t3);
        x10[cc] = y0 + 0.5f * (-t1 + t2 - t3);
        x11[cc] = y0 + 0.5f * (-t1 - t2 + t3);
    }
    int W2 = 2 * W;
    long long ob = (((long long)b * gTot + gOff + g) * (2 * H) + 2 * h) * W2 + 2 * w;
    uint2 r0, r1;
    r0.x = h2bits(x00[0], x00[1]); r0.y = h2bits(x01[0], x01[1]);
    r1.x = h2bits(x10[0], x10[1]); r1.y = h2bits(x11[0], x11[1]);
    *reinterpret_cast<uint2*>(outH2 + ob) = r0;
    *reinterpret_cast<uint2*>(outH2 + ob + W2) = r1;
}

__global__ void iwt_sig_k(const float* __restrict__ in, int H, int W,
                          float* __restrict__ out, int total) {
    int idx = blockIdx.x * blockDim.x + threadIdx.x;
    if (idx >= total) return;
    int w = idx % W; int t = idx / W;
    int h = t % H;  int b = t / H;
    long long s = (long long)H * W;
    long long ib = (((long long)b * 4) * H + h) * W + w;
    float y0 = in[ib];
    float t1 = 2.f * in[ib + s] - 1.f, t2 = 2.f * in[ib + 2 * s] - 1.f, t3 = 2.f * in[ib + 3 * s] - 1.f;
    float x00 = y0 + 0.5f * ( t1 + t2 + t3);
    float x01 = y0 + 0.5f * ( t1 - t2 - t3);
    float x10 = y0 + 0.5f * (-t1 + t2 - t3);
    float x11 = y0 + 0.5f * (-t1 - t2 + t3);
    x00 = 1.f / (1.f + expf(-x00)); x01 = 1.f / (1.f + expf(-x01));
    x10 = 1.f / (1.f + expf(-x10)); x11 = 1.f / (1.f + expf(-x11));
    int W2 = 2 * W;
    float* o = out + ((long long)b * (2 * H) + 2 * h) * W2 + 2 * w;
    o[0] = x00; o[1] = x01; o[W2] = x10; o[W2 + 1] = x11;
}

// ---------------------------------------------------------------------------
// Pipelined fp16 mma conv: COTILE=64, 256 thr, 2 blocks/SM, double-buffered
// (stage -> commit -> wait1 -> sync -> compute -> sync). A via ldmatrix.x4
// from wsm[9][64][12-word rows]. Optional fused wt output (+fp32 wt copy).
// ---------------------------------------------------------------------------
__global__ __launch_bounds__(256, 2)
void conv_mma_pipe_k(const unsigned* __restrict__ inH2, int gInTot, int kTiles,
                     const unsigned* __restrict__ wp, int coutTot,
                     const float* __restrict__ bias,
                     unsigned* __restrict__ outH2, int gOutTot, int gOutOff,
                     unsigned* __restrict__ wtH2, float* __restrict__ wt32,
                     const float* __restrict__ addend, int addCtot,
                     int H, int W) {
    constexpr int PW = 28, GSTRIDE = 18 * PW, PATCH_W = 8 * GSTRIDE;  // 4032
    constexpr int WSM_W = 9 * 64 * 12;                                // 6912
    constexpr int STAGE = PATCH_W + WSM_W;                            // 10944
    extern __shared__ unsigned sm[];
    const int tid = threadIdx.x, lane = tid & 31, warp = tid >> 5;
    const int gid = lane >> 2, tig = lane & 3;
    const int mwarp = warp & 1, nwarp = warp >> 1;
    const int tilesX = W >> 4;
    const int tx0 = (blockIdx.x % tilesX) << 4, ty0 = (blockIdx.x / tilesX) << 4;
    const int co0 = blockIdx.y << 6, b = blockIdx.z;
    const int HW = H * W;
    const long long inBase = (long long)b * gInTot * HW;

    float acc[2][8][4];
#pragma unroll
    for (int mt = 0; mt < 2; mt++)
#pragma unroll
        for (int nt = 0; nt < 8; nt++)
#pragma unroll
            for (int r = 0; r < 4; r++) acc[mt][nt][r] = 0.f;

    auto stage = [&](int kt, int buf) {
        unsigned pb = smem_u32(sm + buf * STAGE);
        unsigned wb = pb + PATCH_W * 4;
        const int g0 = kt * 8;
        for (int idx = tid; idx < 864; idx += 256) {
            int g = idx / 108, rem = idx - g * 108;
            int r = rem / 6, c = rem - r * 6;
            int gy = ty0 - 1 + r, gxs = tx0 - 4 + 4 * c;
            bool ok = (unsigned)gy < (unsigned)H && gxs >= 0 && gxs + 4 <= W;
            const unsigned* src = inH2 + inBase + (long long)(g0 + g) * HW + (ok ? (gy * W + gxs) : 0);
            cp16z(pb + (unsigned)(g * GSTRIDE + r * PW + 4 * c) * 4u, src, ok);
        }
        for (int idx = tid; idx < 1152; idx += 256) {
            int half = idx & 1, row = idx >> 1;     // row = j*64 + co
            int j = row >> 6, co = row & 63;
            const unsigned* src = wp + (((long long)kt * 9 + j) * coutTot + co0 + co) * 8 + half * 4;
            cp16w(wb + (unsigned)((j * 64 + co) * 12 + half * 4) * 4u, src);
        }
    };
    auto compute = [&](int buf) {
        const unsigned* pbuf = sm + buf * STAGE;
        unsigned wbase = smem_u32(sm + buf * STAGE + PATCH_W);
        int lr = lane & 7, hb = (lane >> 3) & 1, kq = (lane >> 4) & 1;
        unsigned aoff0 = wbase + (unsigned)(((mwarp * 32 + hb * 8 + lr) * 12 + kq * 4) << 2);
        unsigned aoff1 = aoff0 + (16 * 12) * 4;
#pragma unroll
        for (int j = 0; j < 9; j++) {
            const int dy = j / 3, dx = j - 3 * dy;
            unsigned a0[4], a1[4];
            ldsm_x4(a0, aoff0 + (unsigned)(j * 768 * 4));
            ldsm_x4(a1, aoff1 + (unsigned)(j * 768 * 4));
            const unsigned* pb0 = pbuf + tig * GSTRIDE + dy * PW + dx + gid + 3;
            const unsigned* pb1 = pbuf + (tig + 4) * GSTRIDE + dy * PW + dx + gid + 3;
#pragma unroll
            for (int nt = 0; nt < 8; nt++) {
                int pix = nwarp * 64 + nt * 8;
                int off = (pix >> 4) * PW + (pix & 15);
                mma16(acc[0][nt], a0, pb0[off], pb1[off]);
                mma16(acc[1][nt], a1, pb0[off], pb1[off]);
            }
        }
    };

    stage(0, 0); cp_commit();
    for (int kt = 0; kt < kTiles; kt++) {
        int cur = kt & 1;
        if (kt + 1 < kTiles) { stage(kt + 1, cur ^ 1); cp_commit(); cp_wait1(); }
        else cp_wait0();
        __syncthreads();
        compute(cur);
        __syncthreads();
    }

    const int Ho = H >> 1, Wo = W >> 1;
#pragma unroll
    for (int mt = 0; mt < 2; mt++)
#pragma unroll
        for (int rr = 0; rr < 2; rr++) {
            int co = co0 + mwarp * 32 + mt * 16 + rr * 8 + gid;
            float bv = bias[co];
#pragma unroll
            for (int np = 0; np < 4; np++) {
                int ntT = (np & 1) | ((np >> 1) << 2);
                int ntB = ntT + 2;
                int pixT = nwarp * 64 + ntT * 8;
                int oy = ty0 + (pixT >> 4);
                int ox = tx0 + (pixT & 15) + 2 * tig;
                float x00 = acc[mt][ntT][rr * 2] + bv, x01 = acc[mt][ntT][rr * 2 + 1] + bv;
                float x10 = acc[mt][ntB][rr * 2] + bv, x11 = acc[mt][ntB][rr * 2 + 1] + bv;
                if (addend) {
                    const float* ap = addend + (((long long)b * addCtot + co) * H + oy) * W + ox;
                    x00 += ap[0]; x01 += ap[1]; x10 += ap[W]; x11 += ap[W + 1];
                }
                x00 = x00 > 0.f ? x00 : 0.2f * x00;
                x01 = x01 > 0.f ? x01 : 0.2f * x01;
                x10 = x10 > 0.f ? x10 : 0.2f * x10;
                x11 = x11 > 0.f ? x11 : 0.2f * x11;
                float sT0 = __shfl_xor_sync(0xffffffffu, x00, 4);
                float sT1 = __shfl_xor_sync(0xffffffffu, x01, 4);
                float sB0 = __shfl_xor_sync(0xffffffffu, x10, 4);
                float sB1 = __shfl_xor_sync(0xffffffffu, x11, 4);
                if ((gid & 1) == 0) {
                    long long ob = (((long long)b * gOutTot + gOutOff + (co >> 1)) * H + oy) * W + ox;
                    uint2 wT, wB;
                    wT.x = h2bits(x00, sT0); wT.y = h2bits(x01, sT1);
                    wB.x = h2bits(x10, sB0); wB.y = h2bits(x11, sB1);
                    *reinterpret_cast<uint2*>(outH2 + ob)     = wT;
                    *reinterpret_cast<uint2*>(outH2 + ob + W) = wB;
                }
                if (wtH2) {
                    float y0 = 0.25f * (x00 + x01 + x10 + x11);
                    float y1 = 0.25f * (x00 + x01 - x10 - x11) + 0.5f;
                    float y2 = 0.25f * (x00 - x01 + x10 - x11) + 0.5f;
                    float y3 = 0.25f * (x00 - x01 - x10 + x11) + 0.5f;
                    int ho = oy >> 1, wo = ox >> 1;
                    long long wbs = (((long long)b * (2 * coutTot) + 2 * co) * Ho + ho) * Wo + wo;
                    wtH2[wbs] = h2bits(y0, y1);
                    wtH2[wbs + (long long)Ho * Wo] = h2bits(y2, y3);
                    if (wt32) {
                        long long fb = (((long long)b * (4 * coutTot) + 4 * co) * Ho + ho) * Wo + wo;
                        long long sw = (long long)Ho * Wo;
                        wt32[fb] = y0; wt32[fb + sw] = y1;
                        wt32[fb + 2 * sw] = y2; wt32[fb + 3 * sw] = y3;
                    }
                }
            }
        }
}

// ----- small-layer mma conv (COTILE=16), optional fused wt -----
__global__ __launch_bounds__(128, 4)
void conv_mma16_k(const unsigned* __restrict__ inH2, int gInTot, int gInAct, int kTiles,
                  const unsigned* __restrict__ wp, int coutPad,
                  const float* __restrict__ bias,
                  float* __restrict__ out32, int out32Ctot,
                  unsigned* __restrict__ outH2, int gOutTot, int gOutOff,
                  unsigned* __restrict__ wtH2, int coutTot,
                  int H, int W, int coutAct) {
    __shared__ unsigned patch[8][18][20];
    __shared__ unsigned wsm[9][8][24];
    const int tid = threadIdx.x, lane = tid & 31, warp = tid >> 5;
    const int gid = lane >> 2, tig = lane & 3;
    const int tilesX = W >> 4;
    const int tx0 = (blockIdx.x % tilesX) << 4, ty0 = (blockIdx.x / tilesX) << 4;
    const int co0 = blockIdx.y * 16, b = blockIdx.z;
    const int HW = H * W;
    float acc[8][4];
#pragma unroll
    for (int nt = 0; nt < 8; nt++)
#pragma unroll
        for (int r = 0; r < 4; r++) acc[nt][r] = 0.f;
    const long long inBase = (long long)b * gInTot * HW;
    for (int kt = 0; kt < kTiles; kt++) {
        const int g0 = kt * 8;
        __syncthreads();
        for (int idx = tid; idx < 8 * 324; idx += 128) {
            int g = idx / 324, rem = idx - g * 324;
            int r = rem / 18, c = rem - r * 18;
            int gy = ty0 - 1 + r, gx = tx0 - 1 + c;
            unsigned v = 0;
            int aG = g0 + g;
            if (aG < gInAct && (unsigned)gy < (unsigned)H && (unsigned)gx < (unsigned)W)
                v = inH2[inBase + (long long)aG * HW + gy * W + gx];
            patch[g][r][c] = v;
        }
        for (int idx = tid; idx < 576; idx += 128) {
            int co2 = idx % 8, t = idx / 8;
            int kg = t % 8, j = t / 8;
            uint2 v = *reinterpret_cast<const uint2*>(
                wp + ((long long)(g0 + kg) * 9 + j) * coutPad + co0 + 2 * co2);
            *reinterpret_cast<uint2*>(&wsm[j][kg][2 * co2]) = v;
        }
        __syncthreads();
#pragma unroll
        for (int j = 0; j < 9; j++) {
            const int dy = j / 3, dx = j - 3 * dy;
            unsigned a[4];
            a[0] = wsm[j][tig][gid];     a[1] = wsm[j][tig][gid + 8];
            a[2] = wsm[j][tig + 4][gid]; a[3] = wsm[j][tig + 4][gid + 8];
            const unsigned* pb0 = &patch[tig][dy][dx + gid];
            const unsigned* pb1 = &patch[tig + 4][dy][dx + gid];
#pragma unroll
            for (int nt = 0; nt < 8; nt++) {
                int pix = warp * 64 + nt * 8;
                int off = (pix >> 4) * 20 + (pix & 15);
                mma16(acc[nt], a, pb0[off], pb1[off]);
            }
        }
    }
    const int Ho = H >> 1, Wo = W >> 1;
#pragma unroll
    for (int rr = 0; rr < 2; rr++) {
        int co = co0 + rr * 8 + gid;
        float bv = (co < coutAct) ? bias[co] : 0.f;
#pragma unroll
        for (int np = 0; np < 4; np++) {
            int ntT = (np & 1) | ((np >> 1) << 2);
            int ntB = ntT + 2;
            int pixT = warp * 64 + ntT * 8;
            int oy = ty0 + (pixT >> 4);
            int ox = tx0 + (pixT & 15) + 2 * tig;
            float x00 = acc[ntT][rr * 2] + bv, x01 = acc[ntT][rr * 2 + 1] + bv;
            float x10 = acc[ntB][rr * 2] + bv, x11 = acc[ntB][rr * 2 + 1] + bv;
            x00 = x00 > 0.f ? x00 : 0.2f * x00;
            x01 = x01 > 0.f ? x01 : 0.2f * x01;
            x10 = x10 > 0.f ? x10 : 0.2f * x10;
            x11 = x11 > 0.f ? x11 : 0.2f * x11;
            if (out32 && co < coutAct) {
                float* op = out32 + (((long long)b * out32Ctot + co) * H + oy) * W + ox;
                *reinterpret_cast<float2*>(op)     = make_float2(x00, x01);
                *reinterpret_cast<float2*>(op + W) = make_float2(x10, x11);
            }
            float sT0 = __shfl_xor_sync(0xffffffffu, x00, 4);
            float sT1 = __shfl_xor_sync(0xffffffffu, x01, 4);
            float sB0 = __shfl_xor_sync(0xffffffffu, x10, 4);
            float sB1 = __shfl_xor_sync(0xffffffffu, x11, 4);
            if (outH2 && (gid & 1) == 0) {
                long long ob = (((long long)b * gOutTot + gOutOff + (co >> 1)) * H + oy) * W + ox;
                uint2 wT, wB;
                wT.x = h2bits(x00, sT0); wT.y = h2bits(x01, sT1);
                wB.x = h2bits(x10, sB0); wB.y = h2bits(x11, sB1);
                *reinterpret_cast<uint2*>(outH2 + ob)     = wT;
                *reinterpret_cast<uint2*>(outH2 + ob + W) = wB;
            }
            if (wtH2 && co < coutAct) {
                float y0 = 0.25f * (x00 + x01 + x10 + x11);
                float y1 = 0.25f * (x00 + x01 - x10 - x11) + 0.5f;
                float y2 = 0.25f * (x00 - x01 + x10 - x11) + 0.5f;
                float y3 = 0.25f * (x00 - x01 - x10 + x11) + 0.5f;
                int ho = oy >> 1, wo = ox >> 1;
                long long wbs = (((long long)b * (2 * coutTot) + 2 * co) * Ho + ho) * Wo + wo;
                wtH2[wbs] = h2bits(y0, y1);
                wtH2[wbs + (long long)Ho * Wo] = h2bits(y2, y3);
            }
        }
    }
}

extern "C" void kernel_launch(void* const* d_in, const int* in_sizes, int n_in,
                              void* d_out, int out_size) {
    const float* x        = (const float*)d_in[0];
    const float* conv1_w  = (const float*)d_in[1];
    const float* conv1_b  = (const float*)d_in[2];
    const float* conv2_w  = (const float*)d_in[3];
    const float* conv2_b  = (const float*)d_in[4];
    const float* conv3_w  = (const float*)d_in[5];
    const float* conv3_b  = (const float*)d_in[6];
    const float* conv4_w  = (const float*)d_in[7];
    const float* conv4_b  = (const float*)d_in[8];
    const float* convd1_w = (const float*)d_in[9];
    const float* convd1_b = (const float*)d_in[10];
    const float* convd2_w = (const float*)d_in[11];
    const float* convd2_b = (const float*)d_in[12];
    const float* convd3_w = (const float*)d_in[13];
    const float* convd3_b = (const float*)d_in[14];
    const float* convd4_w = (const float*)d_in[15];
    const float* convd4_b = (const float*)d_in[16];
    float* out = (float*)d_out;

    float *w4, *iw1;
    unsigned *w1h, *cat2h, *w2h, *cat3h, *w3h, *cat4h, *w4h, *c4h, *c5h;
    unsigned *ic4h, *ic3h, *ic2h, *ic1h;
    unsigned *wp1, *wp2, *wp3, *wp4, *wpd4, *wpd3, *wpd2, *wpd1;
    cudaGetSymbolAddress((void**)&w4, g_w4);
    cudaGetSymbolAddress((void**)&iw1, g_iw1);
    cudaGetSymbolAddress((void**)&w1h, g_w1h);
    cudaGetSymbolAddress((void**)&cat2h, g_cat2h);
    cudaGetSymbolAddress((void**)&w2h, g_w2h);
    cudaGetSymbolAddress((void**)&cat3h, g_cat3h);
    cudaGetSymbolAddress((void**)&w3h, g_w3h);
    cudaGetSymbolAddress((void**)&cat4h, g_cat4h);
    cudaGetSymbolAddress((void**)&w4h, g_w4h);
    cudaGetSymbolAddress((void**)&c4h, g_c4h);
    cudaGetSymbolAddress((void**)&c5h, g_c5h);
    cudaGetSymbolAddress((void**)&ic4h, g_ic4h);
    cudaGetSymbolAddress((void**)&ic3h, g_ic3h);
    cudaGetSymbolAddress((void**)&ic2h, g_ic2h);
    cudaGetSymbolAddress((void**)&ic1h, g_ic1h);
    cudaGetSymbolAddress((void**)&wp1, g_wp1);
    cudaGetSymbolAddress((void**)&wp2, g_wp2);
    cudaGetSymbolAddress((void**)&wp3, g_wp3);
    cudaGetSymbolAddress((void**)&wp4, g_wp4);
    cudaGetSymbolAddress((void**)&wpd4, g_wpd4);
    cudaGetSymbolAddress((void**)&wpd3, g_wpd3);
    cudaGetSymbolAddress((void**)&wpd2, g_wpd2);
    cudaGetSymbolAddress((void**)&wpd1, g_wpd1);

    const int SMEMP = 2 * (4032 + 6912) * 4;   // 87552 B
    static bool attrSet = false;
    if (!attrSet) {
        cudaFuncSetAttribute(conv_mma_pipe_k, cudaFuncAttributeMaxDynamicSharedMemorySize, SMEMP);
        attrSet = true;
    }
    const int B = 8;
    int tot;

    auto packS = [](const float* w, unsigned* outp, int Cin, int CinPad, int Cout, int CoutPad) {
        int K2 = (CinPad / 2) * 9;
        dim3 grid((CoutPad + 31) / 32, (K2 + 31) / 32);
        pack_w_k<<<grid, 256>>>(w, outp, Cin, Cout, CoutPad, K2);
    };
    auto packL = [](const float* w, unsigned* outp, int Cin, int Cout) {
        pack_wL_k<<<dim3(Cout / 32, Cin / 16), 256>>>(w, outp, Cin, Cout);
    };

    packS(conv1_w, wp1, 4, 16, 16, 16);
    packL(conv2_w, wp2, 64, 64);
    tot = B * 256 * 256;
    wt_k<<<(tot + 255) / 256, 256>>>(x, 256, 256, w1h, tot);
    conv_mma16_k<<<dim3(256, 1, 8), 128>>>(w1h, 2, 2, 1, wp1, 16, conv1_b,
                                           nullptr, 0, cat2h, 16, 0, w2h, 16, 256, 256, 16);
    packL(conv3_w, wp3, 256, 256);
    conv_mma_pipe_k<<<dim3(64, 1, 8), 256, SMEMP>>>(w2h, 32, 4, wp2, 64, conv2_b,
        cat3h, 64, 0, w3h, nullptr, nullptr, 0, 128, 128);      // <- ncu sample slot
    packL(conv4_w, wp4, 1024, 1024);
    packL(convd4_w, wpd4, 512, 256);
    packL(convd3_w, wpd3, 128, 64);
    packS(convd2_w, wpd2, 32, 32, 16, 16);
    packS(convd1_w, wpd1, 16, 16, 4, 16);

    conv_mma_pipe_k<<<dim3(16, 4, 8), 256, SMEMP>>>(w3h, 128, 16, wp3, 256, conv3_b,
        cat4h, 256, 0, w4h, w4, nullptr, 0, 64, 64);
    conv_mma_pipe_k<<<dim3(4, 16, 8), 256, SMEMP>>>(w4h, 512, 64, wp4, 1024, conv4_b,
        c4h, 512, 0, nullptr, nullptr, nullptr, 0, 32, 32);
    conv_mma_pipe_k<<<dim3(4, 16, 8), 256, SMEMP>>>(c4h, 512, 64, wp4, 1024, conv4_b,
        c5h, 512, 0, nullptr, nullptr, nullptr, 0, 32, 32);
    conv_mma_pipe_k<<<dim3(4, 16, 8), 256, SMEMP>>>(c5h, 512, 64, wp4, 1024, conv4_b,
        ic4h, 512, 0, nullptr, nullptr, w4, 1024, 32, 32);

    tot = B * 128 * 32 * 32;
    iwt_h2_k<<<(tot + 255) / 256, 256>>>(ic4h, 128, 32, 32, cat4h, 256, 128, tot);

    conv_mma_pipe_k<<<dim3(16, 4, 8), 256, SMEMP>>>(cat4h, 256, 32, wpd4, 256, convd4_b,
        ic3h, 128, 0, nullptr, nullptr, nullptr, 0, 64, 64);
    tot = B * 32 * 64 * 64;
    iwt_h2_k<<<(tot + 255) / 256, 256>>>(ic3h, 32, 64, 64, cat3h, 64, 32, tot);

    conv_mma_pipe_k<<<dim3(64, 1, 8), 256, SMEMP>>>(cat3h, 64, 8, wpd3, 64, convd3_b,
        ic2h, 32, 0, nullptr, nullptr, nullptr, 0, 128, 128);
    tot = B * 8 * 128 * 128;
    iwt_h2_k<<<(tot + 255) / 256, 256>>>(ic2h, 8, 128, 128, cat2h, 16, 8, tot);

    conv_mma16_k<<<dim3(256, 1, 8), 128>>>(cat2h, 16, 16, 2, wpd2, 16, convd2_b,
                                           nullptr, 0, ic1h, 8, 0, nullptr, 16, 256, 256, 16);
    conv_mma16_k<<<dim3(256, 1, 8), 128>>>(ic1h, 8, 8, 1, wpd1, 16, convd1_b,
                                           iw1, 4, nullptr, 0, 0, nullptr, 4, 256, 256, 4);

    tot = B * 256 * 256;
    iwt_sig_k<<<(tot + 255) / 256, 256>>>(iw1, 256, 256, out, tot);

    (void)in_sizes; (void)n_in; (void)out_size;
}